// round 8
// baseline (speedup 1.0000x reference)
#include <cuda_runtime.h>
#include <cstdint>

// ---------------------------------------------------------------------------
// TT embedding lookup R8: chunk = <=8 samples sharing one 256KB core1 slab.
// Work item = (chunk, rowgroup rg of 16 rows, colgroup cg of 256 cols) = 16KB.
// 128-thread CTAs (8/SM), heavy churn: each CTA issues 17.1KB of bulk copies
// at birth (B tile + precomputed A-pack + meta) on one mbarrier, waits once,
// computes, reduces, atomically accumulates. A-packs/meta precomputed by a
// parallel build kernel to remove the per-CTA LDG dependency chain.
// ---------------------------------------------------------------------------

#define NTAB 2
#define BATCH 1024
#define NSAMP (NTAB * BATCH)
#define P12 46656LL
#define NBUCKET (NTAB * 216)
#define CORE1_ROW 65536
#define CHUNK 8
#define MAXCHUNKS 688

struct __align__(16) CMeta { int k; int tbl; int sid[8]; int i2[8]; int pad[14]; };

__device__ int g_offsets[NBUCKET + 1];
__device__ int g_order[NSAMP];
__device__ int g_i0[NSAMP];
__device__ int g_i2[NSAMP];
__device__ int g_chunk_bucket[MAXCHUNKS];
__device__ int g_chunk_start[MAXCHUNKS];
__device__ int g_nchunks;
__device__ __align__(1024) float g_apk[MAXCHUNKS * 2048];  // 5.6MB A-packs
__device__ CMeta g_cmeta[MAXCHUNKS];

// ---------------------------------------------------------------------------
// helpers
// ---------------------------------------------------------------------------
__device__ __forceinline__ unsigned long long pack2(float x, float y) {
    unsigned long long r;
    asm("mov.b64 %0, {%1, %2};" : "=l"(r) : "f"(x), "f"(y));
    return r;
}
__device__ __forceinline__ void unpack2(unsigned long long v, float& x, float& y) {
    asm("mov.b64 {%0, %1}, %2;" : "=f"(x), "=f"(y) : "l"(v));
}
__device__ __forceinline__ void ffma2(unsigned long long& d,
                                      unsigned long long a,
                                      unsigned long long b) {
    asm("fma.rn.f32x2 %0, %1, %2, %0;" : "+l"(d) : "l"(a), "l"(b));
}
__device__ __forceinline__ void mbar_init(uint32_t a, uint32_t cnt) {
    asm volatile("mbarrier.init.shared.b64 [%0], %1;" :: "r"(a), "r"(cnt) : "memory");
}
__device__ __forceinline__ void mbar_expect(uint32_t a, uint32_t bytes) {
    asm volatile("mbarrier.arrive.expect_tx.shared.b64 _, [%0], %1;"
                 :: "r"(a), "r"(bytes) : "memory");
}
__device__ __forceinline__ void mbar_wait(uint32_t a, uint32_t ph) {
    uint32_t done;
    asm volatile(
        "{\n\t.reg .pred p;\n\t"
        "mbarrier.try_wait.parity.acquire.cta.shared::cta.b64 p, [%1], %2;\n\t"
        "selp.b32 %0, 1, 0, p;\n\t}"
        : "=r"(done) : "r"(a), "r"(ph) : "memory");
    if (!done) {
        asm volatile(
            "{\n\t.reg .pred P1;\n"
            "W%=:\n\t"
            "mbarrier.try_wait.parity.acquire.cta.shared::cta.b64 P1, [%0], %1, 0x989680;\n\t"
            "@P1 bra.uni D%=;\n\t"
            "bra.uni W%=;\n"
            "D%=:\n\t}"
            :: "r"(a), "r"(ph) : "memory");
    }
}
__device__ __forceinline__ void bulk_copy(uint32_t dst, const void* src,
                                          uint32_t bytes, uint32_t mbar) {
    asm volatile(
        "cp.async.bulk.shared::cta.global.mbarrier::complete_tx::bytes [%0], [%1], %2, [%3];"
        :: "r"(dst), "l"(src), "r"(bytes), "r"(mbar) : "memory");
}

// ---------------------------------------------------------------------------
// Phase A: decode, bucket-sort (smem atomics), build chunk list, zero output.
// (proven in R5)
// ---------------------------------------------------------------------------
__global__ void build_buckets(const void* __restrict__ idx_raw,
                              float* __restrict__ out) {
    const int tid = threadIdx.x;  // 1024
    __shared__ int   scnt[512];
    __shared__ int   schk[512];
    __shared__ int   scur[NBUCKET];
    __shared__ short sbk[NSAMP];

    float4* o4 = (float4*)out;
    #pragma unroll
    for (int i = tid; i < NSAMP * 4; i += 1024)
        o4[i] = make_float4(0.f, 0.f, 0.f, 0.f);

    if (tid < 512) scnt[tid] = 0;
    __syncthreads();

    const long long* p64 = (const long long*)idx_raw;
    const int*       p32 = (const int*)idx_raw;
    bool is64 = true;
    #pragma unroll
    for (int j = 0; j < 4; j++) {
        long long v = p64[j];
        if (v < 0 || v >= 10000000LL) is64 = false;
    }

    for (int s = tid; s < NSAMP; s += 1024) {
        long long idx = is64 ? p64[s] : (long long)p32[s];
        int i0 = (int)(idx / P12);
        int i1 = (int)((idx / 216) % 216);
        int i2 = (int)(idx % 216);
        int b = (s >> 10) * 216 + i1;
        g_i0[s] = i0;
        g_i2[s] = i2;
        sbk[s] = (short)b;
        atomicAdd(&scnt[b], 1);
    }
    __syncthreads();

    int mycnt = 0;
    if (tid < 512) {
        mycnt = scnt[tid];
        schk[tid] = (mycnt + CHUNK - 1) / CHUNK;
    }
    __syncthreads();
    for (int d = 1; d < 512; d <<= 1) {
        int a = 0, b = 0;
        if (tid < 512 && tid >= d) { a = scnt[tid - d]; b = schk[tid - d]; }
        __syncthreads();
        if (tid < 512 && tid >= d) { scnt[tid] += a; schk[tid] += b; }
        __syncthreads();
    }

    if (tid < NBUCKET) {
        int off = scnt[tid] - mycnt;
        g_offsets[tid] = off;
        scur[tid] = off;
        int nch = (mycnt + CHUNK - 1) / CHUNK;
        int chkoff = schk[tid] - nch;
        for (int j = 0; j < nch; j++) {
            g_chunk_bucket[chkoff + j] = tid;
            g_chunk_start[chkoff + j]  = off + j * CHUNK;
        }
    }
    if (tid == 0) g_offsets[NBUCKET] = NSAMP;
    __syncthreads();
    if (tid == 0) g_nchunks = schk[511];
    __syncthreads();

    for (int s = tid; s < NSAMP; s += 1024) {
        int pos = atomicAdd(&scur[(int)sbk[s]], 1);
        g_order[pos] = s;
    }
}

// ---------------------------------------------------------------------------
// Phase A2: per-chunk A-pack + meta precompute (parallel, one CTA per chunk).
// apk float layout: f = ((Lr*2 + q0)*4 + sp)*2 + l, Lr in [0,128),
// lanes of u64 slot = (sample 2sp, sample 2sp+1). Padded samples -> 0.
// ---------------------------------------------------------------------------
__global__ void build_apk(const float* __restrict__ core0) {
    const int c = blockIdx.x;
    if (c >= g_nchunks) return;
    const int t = threadIdx.x;  // 256

    __shared__ int si0[8], ssid[8], si2[8], sk, stbl;
    if (t == 0) {
        int bucket = g_chunk_bucket[c];
        int cs = g_chunk_start[c];
        int end = g_offsets[bucket + 1];
        sk = min(CHUNK, end - cs);
        stbl = (bucket >= 216) ? 216 * 256 : 0;
    }
    __syncthreads();
    if (t < 8) {
        if (t < sk) {
            int sid = g_order[g_chunk_start[c] + t];
            ssid[t] = sid; si0[t] = g_i0[sid]; si2[t] = g_i2[sid];
        } else {
            ssid[t] = 0; si0[t] = 0; si2[t] = 0;
        }
    }
    __syncthreads();

    if (t == 0) { g_cmeta[c].k = sk; g_cmeta[c].tbl = stbl; }
    if (t < 8)  { g_cmeta[c].sid[t] = ssid[t]; g_cmeta[c].i2[t] = si2[t]; }

    const int k = sk, tbl = stbl;
    #pragma unroll
    for (int f = t; f < 2048; f += 256) {
        int l  = f & 1;
        int e2 = f >> 1;
        int sp = e2 & 3;
        int q0 = (e2 >> 2) & 1;
        int Lr = e2 >> 3;
        int s  = 2 * sp + l;
        float v = 0.0f;
        if (s < k)
            v = __ldg(core0 + tbl + (size_t)si0[s] * 256 + q0 * 128 + Lr);
        g_apk[(size_t)c * 2048 + f] = v;
    }
}

// ---------------------------------------------------------------------------
// Phase B worker: one CTA per (chunk, rg, cg). 128 threads, 2 cols each.
// ---------------------------------------------------------------------------
template <int K2>
__device__ __forceinline__ void run_item(
    const char* __restrict__ sB,
    const unsigned long long* __restrict__ sApk,
    const CMeta* __restrict__ M,
    float (*sRed)[8][4],
    int cg,
    const float* __restrict__ core2,
    float* __restrict__ out) {

    const int t    = threadIdx.x;   // 0..127
    const int lane = t & 31;
    const int warp = t >> 5;        // 0..3

    unsigned long long acc[K2][2][2];
    #pragma unroll
    for (int sp = 0; sp < K2; sp++)
        #pragma unroll
        for (int q0 = 0; q0 < 2; q0++) { acc[sp][q0][0] = 0ULL; acc[sp][q0][1] = 0ULL; }

    #pragma unroll 8
    for (int rr = 0; rr < 16; rr++) {
        float2 b = *(const float2*)(sB + rr * 1024 + t * 8);
        unsigned long long b0 = pack2(b.x, b.x);
        unsigned long long b1 = pack2(b.y, b.y);
        const ulonglong2* ar = (const ulonglong2*)((const char*)sApk + rr * 64);
        #pragma unroll
        for (int q0 = 0; q0 < 2; q0++) {
            ulonglong2 aa = ar[q0 * 2];
            ffma2(acc[0][q0][0], b0, aa.x);
            ffma2(acc[0][q0][1], b1, aa.x);
            if (K2 > 1) { ffma2(acc[1][q0][0], b0, aa.y);
                          ffma2(acc[1][q0][1], b1, aa.y); }
            if (K2 > 2) {
                ulonglong2 ab = ar[q0 * 2 + 1];
                ffma2(acc[2][q0][0], b0, ab.x);
                ffma2(acc[2][q0][1], b1, ab.x);
                if (K2 > 3) { ffma2(acc[3][q0][0], b0, ab.y);
                              ffma2(acc[3][q0][1], b1, ab.y); }
            }
        }
    }

    // Epilogue: contract with C over this CTA's 2 r1 values, warp reduce.
    const int r1p = t & 63;
    const int k = M->k;

    #pragma unroll
    for (int sp = 0; sp < K2; sp++) {
        float x00, x01, x10, x11, y00, y01, y10, y11;
        unpack2(acc[sp][0][0], x00, y00);
        unpack2(acc[sp][0][1], x01, y01);
        unpack2(acc[sp][1][0], x10, y10);
        unpack2(acc[sp][1][1], x11, y11);
        #pragma unroll
        for (int h2 = 0; h2 < 2; h2++) {
            int s = 2 * sp + h2;
            const float* c2row = core2 + M->tbl + (size_t)M->i2[s] * 256;
            float4 cv = __ldg((const float4*)(c2row + r1p * 4));
            float A0 = h2 ? y00 : x00, A1 = h2 ? y01 : x01;
            float B0 = h2 ? y10 : x10, B1 = h2 ? y11 : x11;
            float p00 = fmaf(A0, cv.x, A1 * cv.z);
            float p01 = fmaf(A0, cv.y, A1 * cv.w);
            float p10 = fmaf(B0, cv.x, B1 * cv.z);
            float p11 = fmaf(B0, cv.y, B1 * cv.w);
            #pragma unroll
            for (int off = 16; off > 0; off >>= 1) {
                p00 += __shfl_xor_sync(0xFFFFFFFFu, p00, off);
                p01 += __shfl_xor_sync(0xFFFFFFFFu, p01, off);
                p10 += __shfl_xor_sync(0xFFFFFFFFu, p10, off);
                p11 += __shfl_xor_sync(0xFFFFFFFFu, p11, off);
            }
            if (lane == 0) {
                float* r = sRed[warp][s];
                r[0] = p00; r[1] = p01; r[2] = p10; r[3] = p11;
            }
        }
    }
    __syncthreads();

    if (t < k * 8) {
        int s = t >> 3, j3 = t & 7;
        int q0 = j3 >> 2, q1l = (j3 >> 1) & 1, q2 = j3 & 1;
        int idx = q0 * 2 + q2;
        float v = sRed[2 * q1l][s][idx] + sRed[2 * q1l + 1][s][idx];
        int j = q0 * 8 + (cg * 2 + q1l) * 2 + q2;
        atomicAdd(&out[(size_t)M->sid[s] * 16 + j], v);
    }
}

__global__ __launch_bounds__(128, 8) void tt_worker(
    const float* __restrict__ core1,
    const float* __restrict__ core2,
    float* __restrict__ out) {

    const int bx = blockIdx.x;
    const int c  = bx >> 4;
    if (c >= g_nchunks) return;
    const int e  = bx & 15;
    const int rg = e >> 1;     // row group: rows rg*16 .. +15
    const int cg = e & 1;      // col group: cols cg*256 .. +255

    __shared__ __align__(1024) char sB[16384];
    __shared__ __align__(16) unsigned long long sApk[128];
    __shared__ CMeta sMeta;
    __shared__ float sRed[4][8][4];
    __shared__ __align__(8) unsigned long long sMbar;

    const int t = threadIdx.x;
    const uint32_t mb = (uint32_t)__cvta_generic_to_shared(&sMbar);

    if (t == 0) {
        mbar_init(mb, 1);
        asm volatile("fence.proxy.async.shared::cta;" ::: "memory");
        int bkt = __ldg(&g_chunk_bucket[c]);
        mbar_expect(mb, 16384 + 1024 + 128);
        const float* bsrc = core1 + (size_t)bkt * CORE1_ROW
                          + (size_t)rg * 16 * 512 + cg * 256;
        const uint32_t dstB = (uint32_t)__cvta_generic_to_shared(sB);
        #pragma unroll
        for (int r = 0; r < 16; r++)
            bulk_copy(dstB + r * 1024, bsrc + (size_t)r * 512, 1024, mb);
        bulk_copy((uint32_t)__cvta_generic_to_shared(sApk),
                  g_apk + (size_t)c * 2048 + rg * 256, 1024, mb);
        bulk_copy((uint32_t)__cvta_generic_to_shared(&sMeta),
                  &g_cmeta[c], 128, mb);
    }
    __syncthreads();           // mbar init visible to all before wait
    mbar_wait(mb, 0);

    const int k = sMeta.k;
    switch ((k + 1) >> 1) {
        case 1: run_item<1>(sB, sApk, &sMeta, sRed, cg, core2, out); break;
        case 2: run_item<2>(sB, sApk, &sMeta, sRed, cg, core2, out); break;
        case 3: run_item<3>(sB, sApk, &sMeta, sRed, cg, core2, out); break;
        default: run_item<4>(sB, sApk, &sMeta, sRed, cg, core2, out); break;
    }
}

// ---------------------------------------------------------------------------
// Launch
// ---------------------------------------------------------------------------
extern "C" void kernel_launch(void* const* d_in, const int* in_sizes, int n_in,
                              void* d_out, int out_size) {
    (void)in_sizes; (void)n_in; (void)out_size;
    const void*  idx   = d_in[0];                 // lS_i [2,1024] int64 (or int32)
    const float* core0 = (const float*)d_in[1];   // [2,216,256]
    const float* core1 = (const float*)d_in[2];   // [2,216,65536]
    const float* core2 = (const float*)d_in[3];   // [2,216,256]
    float* out = (float*)d_out;                   // [2,1024,16]

    build_buckets<<<1, 1024>>>(idx, out);
    build_apk<<<MAXCHUNKS, 256>>>(core0);
    tt_worker<<<16 * MAXCHUNKS, 128>>>(core1, core2, out);
}

// round 9
// speedup vs baseline: 1.6949x; 1.6949x over previous
#include <cuda_runtime.h>
#include <cstdint>

// ---------------------------------------------------------------------------
// TT embedding lookup R9: single-burst CTAs.
// Item = (chunk of <=8 samples sharing a 256KB core1 slab, quarter = 32 rows).
// Each 256-thread CTA: at birth issues 4 x 16KB cp.async.bulk on 4 mbarriers
// (64KB in flight immediately), stages A-pack, then each warp free-runs
// through the 4 stages gated only by mbar arrival (no inter-stage syncs,
// buffers never reused). f32x2 FFMA, sample-pair packed accumulators.
// 3 CTAs/SM; DRAM latency covered by ~96KB outstanding per SM.
// ---------------------------------------------------------------------------

#define NTAB 2
#define BATCH 1024
#define NSAMP (NTAB * BATCH)
#define P12 46656LL
#define NBUCKET (NTAB * 216)
#define CORE1_ROW 65536
#define CHUNK 8
#define MAXCHUNKS 688
#define STAGE_BYTES 16384

// dynamic smem layout (bytes)
#define SM_BUF    0          // 4 x 16384 = 65536
#define SM_APK    65536      // 32 rows x 2 q0 x 4 u64 (sample pairs) = 2048
#define SM_RED    67584      // 8 warps x 8 samples x 4 floats = 1024
#define SM_SID    68608      // 8 ints
#define SM_I2     68640
#define SM_I0     68672
#define SM_MBAR   68704      // 4 mbarriers x 8B
#define SM_TOTAL  68736

__device__ int g_offsets[NBUCKET + 1];
__device__ int g_order[NSAMP];
__device__ int g_i0[NSAMP];
__device__ int g_i2[NSAMP];
__device__ int g_chunk_bucket[MAXCHUNKS];
__device__ int g_chunk_start[MAXCHUNKS];
__device__ int g_nchunks;

// ---------------------------------------------------------------------------
// helpers
// ---------------------------------------------------------------------------
__device__ __forceinline__ unsigned long long pack2(float x, float y) {
    unsigned long long r;
    asm("mov.b64 %0, {%1, %2};" : "=l"(r) : "f"(x), "f"(y));
    return r;
}
__device__ __forceinline__ void unpack2(unsigned long long v, float& x, float& y) {
    asm("mov.b64 {%0, %1}, %2;" : "=f"(x), "=f"(y) : "l"(v));
}
__device__ __forceinline__ void ffma2(unsigned long long& d,
                                      unsigned long long a,
                                      unsigned long long b) {
    asm("fma.rn.f32x2 %0, %1, %2, %0;" : "+l"(d) : "l"(a), "l"(b));
}
__device__ __forceinline__ void mbar_init(uint32_t a, uint32_t cnt) {
    asm volatile("mbarrier.init.shared.b64 [%0], %1;" :: "r"(a), "r"(cnt) : "memory");
}
__device__ __forceinline__ void mbar_expect(uint32_t a, uint32_t bytes) {
    asm volatile("mbarrier.arrive.expect_tx.shared.b64 _, [%0], %1;"
                 :: "r"(a), "r"(bytes) : "memory");
}
__device__ __forceinline__ void mbar_wait(uint32_t a, uint32_t ph) {
    uint32_t done;
    asm volatile(
        "{\n\t.reg .pred p;\n\t"
        "mbarrier.try_wait.parity.acquire.cta.shared::cta.b64 p, [%1], %2;\n\t"
        "selp.b32 %0, 1, 0, p;\n\t}"
        : "=r"(done) : "r"(a), "r"(ph) : "memory");
    if (!done) {
        asm volatile(
            "{\n\t.reg .pred P1;\n"
            "W%=:\n\t"
            "mbarrier.try_wait.parity.acquire.cta.shared::cta.b64 P1, [%0], %1, 0x989680;\n\t"
            "@P1 bra.uni D%=;\n\t"
            "bra.uni W%=;\n"
            "D%=:\n\t}"
            :: "r"(a), "r"(ph) : "memory");
    }
}
__device__ __forceinline__ void bulk_copy(uint32_t dst, const void* src,
                                          uint32_t bytes, uint32_t mbar) {
    asm volatile(
        "cp.async.bulk.shared::cta.global.mbarrier::complete_tx::bytes [%0], [%1], %2, [%3];"
        :: "r"(dst), "l"(src), "r"(bytes), "r"(mbar) : "memory");
}

// ---------------------------------------------------------------------------
// Phase A0: zero the output in parallel (atomic accumulation target).
// ---------------------------------------------------------------------------
__global__ void zero_out(float* __restrict__ out) {
    float4* o4 = (float4*)out;
    int i = blockIdx.x * 256 + threadIdx.x;
    if (i < NSAMP * 4) o4[i] = make_float4(0.f, 0.f, 0.f, 0.f);
}

// ---------------------------------------------------------------------------
// Phase A: decode, bucket-sort (smem atomics), build chunk list.
// ---------------------------------------------------------------------------
__global__ void build_buckets(const void* __restrict__ idx_raw) {
    const int tid = threadIdx.x;  // 1024
    __shared__ int   scnt[512];
    __shared__ int   schk[512];
    __shared__ int   scur[NBUCKET];
    __shared__ short sbk[NSAMP];

    if (tid < 512) scnt[tid] = 0;
    __syncthreads();

    const long long* p64 = (const long long*)idx_raw;
    const int*       p32 = (const int*)idx_raw;
    bool is64 = true;
    #pragma unroll
    for (int j = 0; j < 4; j++) {
        long long v = p64[j];
        if (v < 0 || v >= 10000000LL) is64 = false;
    }

    for (int s = tid; s < NSAMP; s += 1024) {
        long long idx = is64 ? p64[s] : (long long)p32[s];
        int i0 = (int)(idx / P12);
        int i1 = (int)((idx / 216) % 216);
        int i2 = (int)(idx % 216);
        int b = (s >> 10) * 216 + i1;
        g_i0[s] = i0;
        g_i2[s] = i2;
        sbk[s] = (short)b;
        atomicAdd(&scnt[b], 1);
    }
    __syncthreads();

    int mycnt = 0;
    if (tid < 512) {
        mycnt = scnt[tid];
        schk[tid] = (mycnt + CHUNK - 1) / CHUNK;
    }
    __syncthreads();
    for (int d = 1; d < 512; d <<= 1) {
        int a = 0, b = 0;
        if (tid < 512 && tid >= d) { a = scnt[tid - d]; b = schk[tid - d]; }
        __syncthreads();
        if (tid < 512 && tid >= d) { scnt[tid] += a; schk[tid] += b; }
        __syncthreads();
    }

    if (tid < NBUCKET) {
        int off = scnt[tid] - mycnt;
        g_offsets[tid] = off;
        scur[tid] = off;
        int nch = (mycnt + CHUNK - 1) / CHUNK;
        int chkoff = schk[tid] - nch;
        for (int j = 0; j < nch; j++) {
            g_chunk_bucket[chkoff + j] = tid;
            g_chunk_start[chkoff + j]  = off + j * CHUNK;
        }
    }
    if (tid == 0) g_offsets[NBUCKET] = NSAMP;
    __syncthreads();
    if (tid == 0) g_nchunks = schk[511];
    __syncthreads();

    for (int s = tid; s < NSAMP; s += 1024) {
        int pos = atomicAdd(&scur[(int)sbk[s]], 1);
        g_order[pos] = s;
    }
}

// ---------------------------------------------------------------------------
// Phase B compute body. K2 = ceil(k/2) sample pairs.
// Thread t covers columns (2t, 2t+1). acc[sp][q0][col] f32x2, lanes =
// (sample 2sp, sample 2sp+1). 4 stages of 8 rows, each in its own buffer;
// no inter-stage synchronization (buffers are write-once).
// ---------------------------------------------------------------------------
template <int K2>
__device__ __forceinline__ void run_chunk(
    char* smem, uint32_t smem_u32, int k,
    const float* __restrict__ c2t,
    float* __restrict__ out) {

    const int t    = threadIdx.x;   // 0..255
    const int lane = t & 31;
    const int warp = t >> 5;        // 0..7

    unsigned long long acc[K2][2][2];
    #pragma unroll
    for (int sp = 0; sp < K2; sp++)
        #pragma unroll
        for (int q0 = 0; q0 < 2; q0++) { acc[sp][q0][0] = 0ULL; acc[sp][q0][1] = 0ULL; }

    const uint32_t mb = smem_u32 + SM_MBAR;

    #pragma unroll 1
    for (int ss = 0; ss < 4; ss++) {
        mbar_wait(mb + ss * 8, 0);

        #pragma unroll
        for (int rr = 0; rr < 8; rr++) {
            float2 b = *(const float2*)(smem + SM_BUF + ss * STAGE_BYTES
                                        + rr * 2048 + t * 8);
            unsigned long long b0 = pack2(b.x, b.x);
            unsigned long long b1 = pack2(b.y, b.y);
            const int Lr = ss * 8 + rr;
            const ulonglong2* ar = (const ulonglong2*)(smem + SM_APK + Lr * 64);
            #pragma unroll
            for (int q0 = 0; q0 < 2; q0++) {
                ulonglong2 aa = ar[q0 * 2];
                ffma2(acc[0][q0][0], b0, aa.x);
                ffma2(acc[0][q0][1], b1, aa.x);
                if (K2 > 1) { ffma2(acc[1][q0][0], b0, aa.y);
                              ffma2(acc[1][q0][1], b1, aa.y); }
                if (K2 > 2) {
                    ulonglong2 ab = ar[q0 * 2 + 1];
                    ffma2(acc[2][q0][0], b0, ab.x);
                    ffma2(acc[2][q0][1], b1, ab.x);
                    if (K2 > 3) { ffma2(acc[3][q0][0], b0, ab.y);
                                  ffma2(acc[3][q0][1], b1, ab.y); }
                }
            }
        }
    }

    // Epilogue: contract with C, warp reduce over r1, combine in smem.
    float* s_red = (float*)(smem + SM_RED);           // [8 warps][8][4]
    const int* s_sid = (const int*)(smem + SM_SID);
    const int* s_i2  = (const int*)(smem + SM_I2);
    const int r1p = t & 63;

    #pragma unroll
    for (int sp = 0; sp < K2; sp++) {
        float x00, x01, x10, x11, y00, y01, y10, y11;
        unpack2(acc[sp][0][0], x00, y00);
        unpack2(acc[sp][0][1], x01, y01);
        unpack2(acc[sp][1][0], x10, y10);
        unpack2(acc[sp][1][1], x11, y11);
        #pragma unroll
        for (int h2 = 0; h2 < 2; h2++) {
            int s = 2 * sp + h2;
            const float* c2row = c2t + (size_t)s_i2[s] * 256;
            float4 cv = __ldg((const float4*)(c2row + r1p * 4));
            float A0 = h2 ? y00 : x00, A1 = h2 ? y01 : x01;
            float B0 = h2 ? y10 : x10, B1 = h2 ? y11 : x11;
            float p00 = fmaf(A0, cv.x, A1 * cv.z);
            float p01 = fmaf(A0, cv.y, A1 * cv.w);
            float p10 = fmaf(B0, cv.x, B1 * cv.z);
            float p11 = fmaf(B0, cv.y, B1 * cv.w);
            #pragma unroll
            for (int off = 16; off > 0; off >>= 1) {
                p00 += __shfl_xor_sync(0xFFFFFFFFu, p00, off);
                p01 += __shfl_xor_sync(0xFFFFFFFFu, p01, off);
                p10 += __shfl_xor_sync(0xFFFFFFFFu, p10, off);
                p11 += __shfl_xor_sync(0xFFFFFFFFu, p11, off);
            }
            if (lane == 0) {
                float* r = s_red + (warp * 8 + s) * 4;
                r[0] = p00; r[1] = p01; r[2] = p10; r[3] = p11;
            }
        }
    }
    __syncthreads();

    if (t < k * 16) {
        int s = t >> 4, j = t & 15;
        int q0 = j >> 3, q1 = (j >> 1) & 3, q2 = j & 1;
        int idx = q0 * 2 + q2;
        int w0 = 2 * q1;
        float v = s_red[((w0)     * 8 + s) * 4 + idx]
                + s_red[((w0 + 1) * 8 + s) * 4 + idx];
        atomicAdd(&out[(size_t)s_sid[s] * 16 + j], v);
    }
}

__global__ __launch_bounds__(256, 3) void tt_burst(
    const float* __restrict__ core0,
    const float* __restrict__ core1,
    const float* __restrict__ core2,
    float* __restrict__ out) {

    extern __shared__ char smem[];
    const int bx = blockIdx.x;
    const int c = bx >> 2;
    const int h = bx & 3;          // quarter: rows 32h..32h+31
    if (c >= g_nchunks) return;

    const uint32_t smem_u32 = (uint32_t)__cvta_generic_to_shared(smem);
    const int t = threadIdx.x;

    // t0: init 4 mbarriers, fence; then warp 0 issues all 4 stage copies.
    if (t == 0) {
        #pragma unroll
        for (int j = 0; j < 4; j++) mbar_init(smem_u32 + SM_MBAR + j * 8, 1);
        asm volatile("fence.proxy.async.shared::cta;" ::: "memory");
    }
    __syncwarp();
    if (t < 4) {
        int bkt = __ldg(&g_chunk_bucket[c]);
        const float* src = core1 + (size_t)bkt * CORE1_ROW
                         + (size_t)h * 32 * 512 + (size_t)t * 4096;
        uint32_t mb = smem_u32 + SM_MBAR + t * 8;
        mbar_expect(mb, STAGE_BYTES);
        bulk_copy(smem_u32 + SM_BUF + t * STAGE_BYTES, src, STAGE_BYTES, mb);
    }

    const int bucket = g_chunk_bucket[c];
    const int cs     = g_chunk_start[c];
    const int end    = g_offsets[bucket + 1];
    const int k      = min(CHUNK, end - cs);
    const int table  = (bucket >= 216) ? 1 : 0;
    const float* c0t = core0 + (size_t)table * 216 * 256;
    const float* c2t = core2 + (size_t)table * 216 * 256;

    int* s_sid = (int*)(smem + SM_SID);
    int* s_i0  = (int*)(smem + SM_I0);
    int* s_i2  = (int*)(smem + SM_I2);
    if (t < CHUNK) {
        if (t < k) {
            int sid = g_order[cs + t];
            s_sid[t] = sid;
            s_i0[t]  = g_i0[sid];
            s_i2[t]  = g_i2[sid];
        } else {
            s_i2[t] = 0;   // safe epilogue loads for padded samples
        }
    }
    // zero A-pack (padded samples contribute 0): 256 u64
    unsigned long long* apk = (unsigned long long*)(smem + SM_APK);
    apk[t] = 0ULL;
    __syncthreads();

    // Stage A sample-pair packs: apk[(Lr*2+q0)*4 + s/2] lanes = (s even, s odd)
    float* apkf = (float*)apk;
    for (int x = t; x < k * 64; x += 256) {
        int s = x >> 6, y = x & 63, q0 = y >> 5, Lr = y & 31;
        float av = __ldg(c0t + (size_t)s_i0[s] * 256 + q0 * 128 + h * 32 + Lr);
        apkf[(((Lr * 2 + q0) * 4) + (s >> 1)) * 2 + (s & 1)] = av;
    }
    __syncthreads();

    switch ((k + 1) >> 1) {
        case 1: run_chunk<1>(smem, smem_u32, k, c2t, out); break;
        case 2: run_chunk<2>(smem, smem_u32, k, c2t, out); break;
        case 3: run_chunk<3>(smem, smem_u32, k, c2t, out); break;
        default: run_chunk<4>(smem, smem_u32, k, c2t, out); break;
    }
}

// ---------------------------------------------------------------------------
// Launch
// ---------------------------------------------------------------------------
extern "C" void kernel_launch(void* const* d_in, const int* in_sizes, int n_in,
                              void* d_out, int out_size) {
    (void)in_sizes; (void)n_in; (void)out_size;
    const void*  idx   = d_in[0];                 // lS_i [2,1024] int64 (or int32)
    const float* core0 = (const float*)d_in[1];   // [2,216,256]
    const float* core1 = (const float*)d_in[2];   // [2,216,65536]
    const float* core2 = (const float*)d_in[3];   // [2,216,256]
    float* out = (float*)d_out;                   // [2,1024,16]

    cudaFuncSetAttribute(tt_burst, cudaFuncAttributeMaxDynamicSharedMemorySize,
                         SM_TOTAL);

    zero_out<<<(NSAMP * 4 + 255) / 256, 256>>>(out);
    build_buckets<<<1, 1024>>>(idx);
    tt_burst<<<4 * MAXCHUNKS, 256, SM_TOTAL>>>(core0, core1, core2, out);
}